// round 1
// baseline (speedup 1.0000x reference)
#include <cuda_runtime.h>
#include <cuda_bf16.h>
#include <math.h>

// ---------------------------------------------------------------------------
// Swin Transformer block, B=16, H=W=56, C=256, NH=8, WS=7, SS=3, HD=32, N=49
// Baseline fp32 implementation: 7 kernels through __device__ scratch.
// ---------------------------------------------------------------------------

#define Bv    16
#define Hv    56
#define Wv    56
#define Cv    256
#define NHv   8
#define WSv   7
#define SSv   3
#define HDv   32
#define Nv    49
#define NWIN  64          // windows per image (8x8)
#define BW    1024        // total windows = Bv * NWIN
#define TOK   50176       // Bv * Hv * Wv  (= BW * Nv)
#define SCALEv 0.17677669529663687f   // 32^-0.5

// scratch (static device allocations are permitted)
__device__ float g_win[TOK * Cv];        // LN1 windows / reused for LN2 output
__device__ float g_qkv[TOK * 3 * Cv];
__device__ float g_atto[TOK * Cv];
__device__ float g_proj[TOK * Cv];
__device__ float g_x1[TOK * Cv];
__device__ float g_hid[TOK * 4 * Cv];

// ---------------------------------------------------------------------------
// LayerNorm kernel. mode==1: read x in (b, i, j) order with cyclic shift and
// write to window-partition order. mode==0: identity token order (LN2).
// One block (256 threads) per output token.
// ---------------------------------------------------------------------------
__global__ void ln_kernel(const float* __restrict__ x,
                          const float* __restrict__ gamma,
                          const float* __restrict__ beta,
                          float* __restrict__ out, int mode)
{
    int t   = blockIdx.x;
    int tid = threadIdx.x;
    int src;
    if (mode == 1) {
        int win = t / Nv, n = t % Nv;
        int b = win / NWIN, w = win % NWIN;
        int i = (w / 8) * WSv + n / WSv;
        int j = (w % 8) * WSv + n % WSv;
        int si = (i + SSv) % Hv;
        int sj = (j + SSv) % Wv;
        src = b * (Hv * Wv) + si * Wv + sj;
    } else {
        src = t;
    }

    float v = x[src * Cv + tid];
    // block reduction for mean / var
    float s = v, s2 = v * v;
    #pragma unroll
    for (int o = 16; o > 0; o >>= 1) {
        s  += __shfl_xor_sync(0xffffffffu, s,  o);
        s2 += __shfl_xor_sync(0xffffffffu, s2, o);
    }
    __shared__ float ws[8], ws2[8], stat[2];
    int wid = tid >> 5, lid = tid & 31;
    if (lid == 0) { ws[wid] = s; ws2[wid] = s2; }
    __syncthreads();
    if (tid == 0) {
        float a = 0.f, a2 = 0.f;
        #pragma unroll
        for (int k = 0; k < 8; k++) { a += ws[k]; a2 += ws2[k]; }
        float mu  = a * (1.f / Cv);
        float var = a2 * (1.f / Cv) - mu * mu;
        stat[0] = mu;
        stat[1] = rsqrtf(var + 1e-5f);
    }
    __syncthreads();
    float mu = stat[0], rstd = stat[1];
    out[t * Cv + tid] = (v - mu) * rstd * gamma[tid] + beta[tid];
}

// ---------------------------------------------------------------------------
// SGEMM: C[M,Nc] = A[M,K] @ W^T  (W row-major [Nc,K]) + bias, optional exact
// GELU (act==1), optional residual add (res != nullptr, layout M x Nc).
// 128x128 tile, BK=8, 256 threads, 8x8 per thread.
// M % 128 == 0, Nc % 128 == 0, K % 8 == 0 (all true for this problem).
// ---------------------------------------------------------------------------
__global__ __launch_bounds__(256) void sgemm_kernel(
    const float* __restrict__ A, const float* __restrict__ Wt,
    const float* __restrict__ bias, const float* __restrict__ res,
    float* __restrict__ Cout, int M, int Nc, int K, int act)
{
    __shared__ float As[8][128];
    __shared__ float Bs[8][128];

    int tid = threadIdx.x;
    int tx = tid & 15, ty = tid >> 4;
    int bm = blockIdx.y * 128, bn = blockIdx.x * 128;

    int lr = tid >> 1;          // 0..127
    int lc = (tid & 1) * 4;     // 0 or 4

    float acc[8][8];
    #pragma unroll
    for (int i = 0; i < 8; i++)
        #pragma unroll
        for (int j = 0; j < 8; j++) acc[i][j] = 0.f;

    const float* Arow = A  + (size_t)(bm + lr) * K + lc;
    const float* Brow = Wt + (size_t)(bn + lr) * K + lc;

    for (int k0 = 0; k0 < K; k0 += 8) {
        float4 a4 = *(const float4*)(Arow + k0);
        float4 b4 = *(const float4*)(Brow + k0);
        __syncthreads();
        As[lc + 0][lr] = a4.x; As[lc + 1][lr] = a4.y;
        As[lc + 2][lr] = a4.z; As[lc + 3][lr] = a4.w;
        Bs[lc + 0][lr] = b4.x; Bs[lc + 1][lr] = b4.y;
        Bs[lc + 2][lr] = b4.z; Bs[lc + 3][lr] = b4.w;
        __syncthreads();
        #pragma unroll
        for (int kk = 0; kk < 8; kk++) {
            float a[8], b[8];
            float4 t0 = *(const float4*)&As[kk][ty * 4];
            float4 t1 = *(const float4*)&As[kk][64 + ty * 4];
            float4 u0 = *(const float4*)&Bs[kk][tx * 4];
            float4 u1 = *(const float4*)&Bs[kk][64 + tx * 4];
            a[0]=t0.x; a[1]=t0.y; a[2]=t0.z; a[3]=t0.w;
            a[4]=t1.x; a[5]=t1.y; a[6]=t1.z; a[7]=t1.w;
            b[0]=u0.x; b[1]=u0.y; b[2]=u0.z; b[3]=u0.w;
            b[4]=u1.x; b[5]=u1.y; b[6]=u1.z; b[7]=u1.w;
            #pragma unroll
            for (int i = 0; i < 8; i++)
                #pragma unroll
                for (int j = 0; j < 8; j++)
                    acc[i][j] = fmaf(a[i], b[j], acc[i][j]);
        }
    }

    #pragma unroll
    for (int i = 0; i < 8; i++) {
        int row = bm + ((i < 4) ? (ty * 4 + i) : (64 + ty * 4 + i - 4));
        #pragma unroll
        for (int j = 0; j < 8; j++) {
            int col = bn + ((j < 4) ? (tx * 4 + j) : (64 + tx * 4 + j - 4));
            float v = acc[i][j];
            if (bias) v += bias[col];
            if (act == 1)
                v = 0.5f * v * (1.f + erff(v * 0.70710678118654752f));
            size_t oidx = (size_t)row * Nc + col;
            if (res) v += res[oidx];
            Cout[oidx] = v;
        }
    }
}

// ---------------------------------------------------------------------------
// Window attention: one block per (window, head). 256 threads.
// qkv layout per token: [3, NH, HD] features. out layout (BW*N, C).
// ---------------------------------------------------------------------------
__global__ __launch_bounds__(256) void attn_kernel(
    const float* __restrict__ qkv, const float* __restrict__ rel_bias,
    const float* __restrict__ mask, float* __restrict__ out)
{
    int blk  = blockIdx.x;
    int win  = blk >> 3;       // / NHv
    int head = blk & 7;
    int tid  = threadIdx.x;

    __shared__ float qs[Nv * HDv];
    __shared__ float ks[Nv * HDv];
    __shared__ float vs[Nv * HDv];
    __shared__ float att[Nv * Nv];

    int base = win * Nv;
    for (int idx = tid; idx < Nv * HDv; idx += 256) {
        int n = idx >> 5, d = idx & 31;
        int row = (base + n) * (3 * Cv);
        int f   = head * HDv + d;
        qs[idx] = qkv[row + f] * SCALEv;
        ks[idx] = qkv[row + Cv + f];
        vs[idx] = qkv[row + 2 * Cv + f];
    }
    __syncthreads();

    int wm = win % NWIN;
    for (int e = tid; e < Nv * Nv; e += 256) {
        int n = e / Nv, m = e % Nv;
        float s = 0.f;
        #pragma unroll
        for (int d = 0; d < HDv; d++)
            s = fmaf(qs[n * HDv + d], ks[m * HDv + d], s);
        int r1 = n / WSv, c1 = n % WSv;
        int r2 = m / WSv, c2 = m % WSv;
        int bi = (r1 - r2 + WSv - 1) * (2 * WSv - 1) + (c1 - c2 + WSv - 1);
        s += rel_bias[bi * NHv + head] + mask[wm * (Nv * Nv) + e];
        att[e] = s;
    }
    __syncthreads();

    if (tid < Nv) {
        float mx = -1e30f;
        #pragma unroll 7
        for (int m = 0; m < Nv; m++) mx = fmaxf(mx, att[tid * Nv + m]);
        float sum = 0.f;
        #pragma unroll 7
        for (int m = 0; m < Nv; m++) {
            float e2 = __expf(att[tid * Nv + m] - mx);
            att[tid * Nv + m] = e2;
            sum += e2;
        }
        float inv = 1.f / sum;
        #pragma unroll 7
        for (int m = 0; m < Nv; m++) att[tid * Nv + m] *= inv;
    }
    __syncthreads();

    for (int idx = tid; idx < Nv * HDv; idx += 256) {
        int n = idx >> 5, d = idx & 31;
        float s = 0.f;
        #pragma unroll 7
        for (int m = 0; m < Nv; m++)
            s = fmaf(att[n * Nv + m], vs[m * HDv + d], s);
        out[(size_t)(base + n) * Cv + head * HDv + d] = s;
    }
}

// ---------------------------------------------------------------------------
// Window-reverse + reverse cyclic shift + residual: x1 = x + unshift(proj)
// One block per token (b,i,j), 256 threads = channels.
// ---------------------------------------------------------------------------
__global__ void unshift_add_kernel(const float* __restrict__ x,
                                   const float* __restrict__ proj,
                                   float* __restrict__ x1)
{
    int tok = blockIdx.x;
    int c   = threadIdx.x;
    int b = tok / (Hv * Wv);
    int ij = tok % (Hv * Wv);
    int i = ij / Wv, j = ij % Wv;
    int p = (i + Hv - SSv) % Hv;
    int q = (j + Wv - SSv) % Wv;
    int win = b * NWIN + (p / WSv) * 8 + (q / WSv);
    int n   = (p % WSv) * WSv + (q % WSv);
    size_t oidx = (size_t)tok * Cv + c;
    x1[oidx] = x[oidx] + proj[(size_t)(win * Nv + n) * Cv + c];
}

// ---------------------------------------------------------------------------
extern "C" void kernel_launch(void* const* d_in, const int* in_sizes, int n_in,
                              void* d_out, int out_size)
{
    const float* x       = (const float*)d_in[0];
    const float* mask    = (const float*)d_in[1];
    const float* norm1_g = (const float*)d_in[2];
    const float* norm1_b = (const float*)d_in[3];
    const float* qkv_w   = (const float*)d_in[4];
    const float* qkv_b   = (const float*)d_in[5];
    const float* rel_bias= (const float*)d_in[6];
    const float* proj_w  = (const float*)d_in[7];
    const float* proj_b  = (const float*)d_in[8];
    const float* norm2_g = (const float*)d_in[9];
    const float* norm2_b = (const float*)d_in[10];
    const float* fc1_w   = (const float*)d_in[11];
    const float* fc1_b   = (const float*)d_in[12];
    const float* fc2_w   = (const float*)d_in[13];
    const float* fc2_b   = (const float*)d_in[14];
    float* out = (float*)d_out;

    float *p_win, *p_qkv, *p_atto, *p_proj, *p_x1, *p_hid;
    cudaGetSymbolAddress((void**)&p_win,  g_win);
    cudaGetSymbolAddress((void**)&p_qkv,  g_qkv);
    cudaGetSymbolAddress((void**)&p_atto, g_atto);
    cudaGetSymbolAddress((void**)&p_proj, g_proj);
    cudaGetSymbolAddress((void**)&p_x1,   g_x1);
    cudaGetSymbolAddress((void**)&p_hid,  g_hid);

    // 1. LN1 + shift + window partition
    ln_kernel<<<TOK, 256>>>(x, norm1_g, norm1_b, p_win, 1);

    // 2. QKV GEMM: (50176,256) x (768,256)^T
    {
        dim3 grid(3 * Cv / 128, TOK / 128);
        sgemm_kernel<<<grid, 256>>>(p_win, qkv_w, qkv_b, nullptr, p_qkv,
                                    TOK, 3 * Cv, Cv, 0);
    }

    // 3. window attention
    attn_kernel<<<BW * NHv, 256>>>(p_qkv, rel_bias, mask, p_atto);

    // 4. proj GEMM
    {
        dim3 grid(Cv / 128, TOK / 128);
        sgemm_kernel<<<grid, 256>>>(p_atto, proj_w, proj_b, nullptr, p_proj,
                                    TOK, Cv, Cv, 0);
    }

    // 5. window reverse + unshift + residual -> x1
    unshift_add_kernel<<<TOK, 256>>>(x, p_proj, p_x1);

    // 6. LN2
    ln_kernel<<<TOK, 256>>>(p_x1, norm2_g, norm2_b, p_win, 0);

    // 7. fc1 GEMM + exact GELU
    {
        dim3 grid(4 * Cv / 128, TOK / 128);
        sgemm_kernel<<<grid, 256>>>(p_win, fc1_w, fc1_b, nullptr, p_hid,
                                    TOK, 4 * Cv, Cv, 1);
    }

    // 8. fc2 GEMM + residual(x1) -> out
    {
        dim3 grid(Cv / 128, TOK / 128);
        sgemm_kernel<<<grid, 256>>>(p_hid, fc2_w, fc2_b, p_x1, out,
                                    TOK, Cv, 4 * Cv, 0);
    }
}

// round 3
// speedup vs baseline: 1.3039x; 1.3039x over previous
#include <cuda_runtime.h>
#include <cuda_bf16.h>
#include <math.h>
#include <stdint.h>

// ---------------------------------------------------------------------------
// Swin Transformer block, B=16, H=W=56, C=256, NH=8, WS=7, SS=3, HD=32, N=49
// R2: resubmit of R1 (infra failure) — TF32 tensor-core GEMMs.
// ---------------------------------------------------------------------------

#define Bv    16
#define Hv    56
#define Wv    56
#define Cv    256
#define NHv   8
#define WSv   7
#define SSv   3
#define HDv   32
#define Nv    49
#define NWIN  64
#define BW    1024
#define TOK   50176
#define SCALEv 0.17677669529663687f

__device__ float g_win[TOK * Cv];
__device__ float g_qkv[TOK * 3 * Cv];
__device__ float g_atto[TOK * Cv];
__device__ float g_proj[TOK * Cv];
__device__ float g_x1[TOK * Cv];
__device__ float g_hid[TOK * 4 * Cv];

// ---------------------------------------------------------------------------
// LayerNorm (mode 1: +shift+window-partition reorder; mode 0: identity order)
// ---------------------------------------------------------------------------
__global__ void ln_kernel(const float* __restrict__ x,
                          const float* __restrict__ gamma,
                          const float* __restrict__ beta,
                          float* __restrict__ out, int mode)
{
    int t   = blockIdx.x;
    int tid = threadIdx.x;
    int src;
    if (mode == 1) {
        int win = t / Nv, n = t % Nv;
        int b = win / NWIN, w = win % NWIN;
        int i = (w / 8) * WSv + n / WSv;
        int j = (w % 8) * WSv + n % WSv;
        int si = (i + SSv) % Hv;
        int sj = (j + SSv) % Wv;
        src = b * (Hv * Wv) + si * Wv + sj;
    } else {
        src = t;
    }

    float v = x[src * Cv + tid];
    float s = v, s2 = v * v;
    #pragma unroll
    for (int o = 16; o > 0; o >>= 1) {
        s  += __shfl_xor_sync(0xffffffffu, s,  o);
        s2 += __shfl_xor_sync(0xffffffffu, s2, o);
    }
    __shared__ float ws[8], ws2[8], stat[2];
    int wid = tid >> 5, lid = tid & 31;
    if (lid == 0) { ws[wid] = s; ws2[wid] = s2; }
    __syncthreads();
    if (tid == 0) {
        float a = 0.f, a2 = 0.f;
        #pragma unroll
        for (int k = 0; k < 8; k++) { a += ws[k]; a2 += ws2[k]; }
        float mu  = a * (1.f / Cv);
        float var = a2 * (1.f / Cv) - mu * mu;
        stat[0] = mu;
        stat[1] = rsqrtf(var + 1e-5f);
    }
    __syncthreads();
    float mu = stat[0], rstd = stat[1];
    out[t * Cv + tid] = (v - mu) * rstd * gamma[tid] + beta[tid];
}

// ---------------------------------------------------------------------------
// TF32 tensor-core GEMM: C[M,Nc] = A[M,K] @ Wt^T + bias (+GELU)(+res)
// Wt row-major [Nc,K]. BM=BN=128, BK=16, 256 thr = 8 warps (2x4),
// warp tile 64x32 via mma.sync.m16n8k8.tf32, fp32 accumulate.
// Requires M%128==0, Nc%128==0, K%16==0.
// ---------------------------------------------------------------------------
#define PAD 4
__device__ __forceinline__ uint32_t f2tf32(float f) {
    uint32_t r;
    asm("cvt.rna.tf32.f32 %0, %1;" : "=r"(r) : "f"(f));
    return r;
}
__device__ __forceinline__ void mma_tf32(float* c, const uint32_t* a, const uint32_t* b) {
    asm volatile(
        "mma.sync.aligned.m16n8k8.row.col.f32.tf32.tf32.f32 "
        "{%0,%1,%2,%3}, {%4,%5,%6,%7}, {%8,%9}, {%0,%1,%2,%3};"
        : "+f"(c[0]), "+f"(c[1]), "+f"(c[2]), "+f"(c[3])
        : "r"(a[0]), "r"(a[1]), "r"(a[2]), "r"(a[3]), "r"(b[0]), "r"(b[1]));
}

__global__ __launch_bounds__(256) void tf32_gemm_kernel(
    const float* __restrict__ A, const float* __restrict__ Wt,
    const float* __restrict__ bias, const float* __restrict__ res,
    float* __restrict__ Cout, int M, int Nc, int K, int act)
{
    __shared__ uint32_t As[16][128 + PAD];
    __shared__ uint32_t Bs[16][128 + PAD];

    int tid  = threadIdx.x;
    int warp = tid >> 5, lane = tid & 31;
    int wm   = (warp >> 2) * 64;
    int wn   = (warp & 3) * 32;
    int bm   = blockIdx.y * 128, bn = blockIdx.x * 128;

    float acc[4][4][4];
    #pragma unroll
    for (int mt = 0; mt < 4; mt++)
        #pragma unroll
        for (int nt = 0; nt < 4; nt++)
            #pragma unroll
            for (int i = 0; i < 4; i++) acc[mt][nt][i] = 0.f;

    const float* Aptr = A  + (size_t)bm * K;
    const float* Bptr = Wt + (size_t)bn * K;

    int idx0 = tid, idx1 = tid + 256;
    int ar0 = idx0 >> 2, ac0 = (idx0 & 3) * 4;
    int ar1 = idx1 >> 2, ac1 = (idx1 & 3) * 4;

    float4 a_reg[2], b_reg[2];
    a_reg[0] = *(const float4*)(Aptr + (size_t)ar0 * K + ac0);
    a_reg[1] = *(const float4*)(Aptr + (size_t)ar1 * K + ac1);
    b_reg[0] = *(const float4*)(Bptr + (size_t)ar0 * K + ac0);
    b_reg[1] = *(const float4*)(Bptr + (size_t)ar1 * K + ac1);

    for (int k0 = 0; k0 < K; k0 += 16) {
        __syncthreads();
        As[ac0 + 0][ar0] = f2tf32(a_reg[0].x);
        As[ac0 + 1][ar0] = f2tf32(a_reg[0].y);
        As[ac0 + 2][ar0] = f2tf32(a_reg[0].z);
        As[ac0 + 3][ar0] = f2tf32(a_reg[0].w);
        As[ac1 + 0][ar1] = f2tf32(a_reg[1].x);
        As[ac1 + 1][ar1] = f2tf32(a_reg[1].y);
        As[ac1 + 2][ar1] = f2tf32(a_reg[1].z);
        As[ac1 + 3][ar1] = f2tf32(a_reg[1].w);
        Bs[ac0 + 0][ar0] = f2tf32(b_reg[0].x);
        Bs[ac0 + 1][ar0] = f2tf32(b_reg[0].y);
        Bs[ac0 + 2][ar0] = f2tf32(b_reg[0].z);
        Bs[ac0 + 3][ar0] = f2tf32(b_reg[0].w);
        Bs[ac1 + 0][ar1] = f2tf32(b_reg[1].x);
        Bs[ac1 + 1][ar1] = f2tf32(b_reg[1].y);
        Bs[ac1 + 2][ar1] = f2tf32(b_reg[1].z);
        Bs[ac1 + 3][ar1] = f2tf32(b_reg[1].w);
        __syncthreads();

        if (k0 + 16 < K) {
            int kn = k0 + 16;
            a_reg[0] = *(const float4*)(Aptr + (size_t)ar0 * K + kn + ac0);
            a_reg[1] = *(const float4*)(Aptr + (size_t)ar1 * K + kn + ac1);
            b_reg[0] = *(const float4*)(Bptr + (size_t)ar0 * K + kn + ac0);
            b_reg[1] = *(const float4*)(Bptr + (size_t)ar1 * K + kn + ac1);
        }

        #pragma unroll
        for (int ks = 0; ks < 2; ks++) {
            int kb = ks * 8;
            int qr = lane >> 2, qc = lane & 3;
            uint32_t af[4][4], bf[4][2];
            #pragma unroll
            for (int mt = 0; mt < 4; mt++) {
                int m = wm + mt * 16 + qr;
                af[mt][0] = As[kb + qc][m];
                af[mt][1] = As[kb + qc][m + 8];
                af[mt][2] = As[kb + qc + 4][m];
                af[mt][3] = As[kb + qc + 4][m + 8];
            }
            #pragma unroll
            for (int nt = 0; nt < 4; nt++) {
                int n = wn + nt * 8 + qr;
                bf[nt][0] = Bs[kb + qc][n];
                bf[nt][1] = Bs[kb + qc + 4][n];
            }
            #pragma unroll
            for (int mt = 0; mt < 4; mt++)
                #pragma unroll
                for (int nt = 0; nt < 4; nt++)
                    mma_tf32(acc[mt][nt], af[mt], bf[nt]);
        }
    }

    // epilogue
    const float INV_SQRT2 = 0.70710678118654752f;
    int qr = lane >> 2, qc = lane & 3;
    #pragma unroll
    for (int mt = 0; mt < 4; mt++) {
        #pragma unroll
        for (int half = 0; half < 2; half++) {
            int row = bm + wm + mt * 16 + qr + half * 8;
            #pragma unroll
            for (int nt = 0; nt < 4; nt++) {
                int col = bn + wn + nt * 8 + qc * 2;
                float v0 = acc[mt][nt][half * 2 + 0];
                float v1 = acc[mt][nt][half * 2 + 1];
                if (bias) { v0 += bias[col]; v1 += bias[col + 1]; }
                if (act == 1) {
                    v0 = 0.5f * v0 * (1.f + erff(v0 * INV_SQRT2));
                    v1 = 0.5f * v1 * (1.f + erff(v1 * INV_SQRT2));
                }
                size_t oidx = (size_t)row * Nc + col;
                if (res) { v0 += res[oidx]; v1 += res[oidx + 1]; }
                *(float2*)(Cout + oidx) = make_float2(v0, v1);
            }
        }
    }
}

// ---------------------------------------------------------------------------
// Window attention: one block per (window, head). 256 threads.
// ---------------------------------------------------------------------------
__global__ __launch_bounds__(256) void attn_kernel(
    const float* __restrict__ qkv, const float* __restrict__ rel_bias,
    const float* __restrict__ mask, float* __restrict__ out)
{
    int blk  = blockIdx.x;
    int win  = blk >> 3;
    int head = blk & 7;
    int tid  = threadIdx.x;

    __shared__ float qs[Nv * HDv];
    __shared__ float ks[Nv * HDv];
    __shared__ float vs[Nv * HDv];
    __shared__ float att[Nv * Nv];

    int base = win * Nv;
    for (int idx = tid; idx < Nv * HDv; idx += 256) {
        int n = idx >> 5, d = idx & 31;
        int row = (base + n) * (3 * Cv);
        int f   = head * HDv + d;
        qs[idx] = qkv[row + f] * SCALEv;
        ks[idx] = qkv[row + Cv + f];
        vs[idx] = qkv[row + 2 * Cv + f];
    }
    __syncthreads();

    int wm = win % NWIN;
    for (int e = tid; e < Nv * Nv; e += 256) {
        int n = e / Nv, m = e % Nv;
        float s = 0.f;
        #pragma unroll
        for (int d = 0; d < HDv; d++)
            s = fmaf(qs[n * HDv + d], ks[m * HDv + d], s);
        int r1 = n / WSv, c1 = n % WSv;
        int r2 = m / WSv, c2 = m % WSv;
        int bi = (r1 - r2 + WSv - 1) * (2 * WSv - 1) + (c1 - c2 + WSv - 1);
        s += rel_bias[bi * NHv + head] + mask[wm * (Nv * Nv) + e];
        att[e] = s;
    }
    __syncthreads();

    if (tid < Nv) {
        float mx = -1e30f;
        #pragma unroll 7
        for (int m = 0; m < Nv; m++) mx = fmaxf(mx, att[tid * Nv + m]);
        float sum = 0.f;
        #pragma unroll 7
        for (int m = 0; m < Nv; m++) {
            float e2 = __expf(att[tid * Nv + m] - mx);
            att[tid * Nv + m] = e2;
            sum += e2;
        }
        float inv = 1.f / sum;
        #pragma unroll 7
        for (int m = 0; m < Nv; m++) att[tid * Nv + m] *= inv;
    }
    __syncthreads();

    for (int idx = tid; idx < Nv * HDv; idx += 256) {
        int n = idx >> 5, d = idx & 31;
        float s = 0.f;
        #pragma unroll 7
        for (int m = 0; m < Nv; m++)
            s = fmaf(att[n * Nv + m], vs[m * HDv + d], s);
        out[(size_t)(base + n) * Cv + head * HDv + d] = s;
    }
}

// ---------------------------------------------------------------------------
__global__ void unshift_add_kernel(const float* __restrict__ x,
                                   const float* __restrict__ proj,
                                   float* __restrict__ x1)
{
    int tok = blockIdx.x;
    int c   = threadIdx.x;
    int b = tok / (Hv * Wv);
    int ij = tok % (Hv * Wv);
    int i = ij / Wv, j = ij % Wv;
    int p = (i + Hv - SSv) % Hv;
    int q = (j + Wv - SSv) % Wv;
    int win = b * NWIN + (p / WSv) * 8 + (q / WSv);
    int n   = (p % WSv) * WSv + (q % WSv);
    size_t oidx = (size_t)tok * Cv + c;
    x1[oidx] = x[oidx] + proj[(size_t)(win * Nv + n) * Cv + c];
}

// ---------------------------------------------------------------------------
extern "C" void kernel_launch(void* const* d_in, const int* in_sizes, int n_in,
                              void* d_out, int out_size)
{
    const float* x       = (const float*)d_in[0];
    const float* mask    = (const float*)d_in[1];
    const float* norm1_g = (const float*)d_in[2];
    const float* norm1_b = (const float*)d_in[3];
    const float* qkv_w   = (const float*)d_in[4];
    const float* qkv_b   = (const float*)d_in[5];
    const float* rel_bias= (const float*)d_in[6];
    const float* proj_w  = (const float*)d_in[7];
    const float* proj_b  = (const float*)d_in[8];
    const float* norm2_g = (const float*)d_in[9];
    const float* norm2_b = (const float*)d_in[10];
    const float* fc1_w   = (const float*)d_in[11];
    const float* fc1_b   = (const float*)d_in[12];
    const float* fc2_w   = (const float*)d_in[13];
    const float* fc2_b   = (const float*)d_in[14];
    float* out = (float*)d_out;

    float *p_win, *p_qkv, *p_atto, *p_proj, *p_x1, *p_hid;
    cudaGetSymbolAddress((void**)&p_win,  g_win);
    cudaGetSymbolAddress((void**)&p_qkv,  g_qkv);
    cudaGetSymbolAddress((void**)&p_atto, g_atto);
    cudaGetSymbolAddress((void**)&p_proj, g_proj);
    cudaGetSymbolAddress((void**)&p_x1,   g_x1);
    cudaGetSymbolAddress((void**)&p_hid,  g_hid);

    // 1. LN1 + shift + window partition
    ln_kernel<<<TOK, 256>>>(x, norm1_g, norm1_b, p_win, 1);

    // 2. QKV GEMM
    {
        dim3 grid(3 * Cv / 128, TOK / 128);
        tf32_gemm_kernel<<<grid, 256>>>(p_win, qkv_w, qkv_b, nullptr, p_qkv,
                                        TOK, 3 * Cv, Cv, 0);
    }

    // 3. window attention
    attn_kernel<<<BW * NHv, 256>>>(p_qkv, rel_bias, mask, p_atto);

    // 4. proj GEMM
    {
        dim3 grid(Cv / 128, TOK / 128);
        tf32_gemm_kernel<<<grid, 256>>>(p_atto, proj_w, proj_b, nullptr, p_proj,
                                        TOK, Cv, Cv, 0);
    }

    // 5. window reverse + unshift + residual -> x1
    unshift_add_kernel<<<TOK, 256>>>(x, p_proj, p_x1);

    // 6. LN2
    ln_kernel<<<TOK, 256>>>(p_x1, norm2_g, norm2_b, p_win, 0);

    // 7. fc1 GEMM + GELU
    {
        dim3 grid(4 * Cv / 128, TOK / 128);
        tf32_gemm_kernel<<<grid, 256>>>(p_win, fc1_w, fc1_b, nullptr, p_hid,
                                        TOK, 4 * Cv, Cv, 1);
    }

    // 8. fc2 GEMM + residual(x1) -> out
    {
        dim3 grid(Cv / 128, TOK / 128);
        tf32_gemm_kernel<<<grid, 256>>>(p_hid, fc2_w, fc2_b, p_x1, out,
                                        TOK, Cv, 4 * Cv, 0);
    }
}

// round 6
// speedup vs baseline: 3.3434x; 2.5642x over previous
#include <cuda_runtime.h>
#include <cuda_bf16.h>
#include <math.h>
#include <stdint.h>

// ---------------------------------------------------------------------------
// Swin Transformer block, B=16, H=W=56, C=256, NH=8, WS=7, SS=3, HD=32, N=49
// R3: fix 32-way bank conflicts in attention QK (K stored transposed),
//     warp-per-token LN with float4, vectorized unshift.
// ---------------------------------------------------------------------------

#define Bv    16
#define Hv    56
#define Wv    56
#define Cv    256
#define NHv   8
#define WSv   7
#define SSv   3
#define HDv   32
#define Nv    49
#define NWIN  64
#define BW    1024
#define TOK   50176
#define SCALEv 0.17677669529663687f

__device__ float g_win[TOK * Cv];
__device__ float g_qkv[TOK * 3 * Cv];
__device__ float g_atto[TOK * Cv];
__device__ float g_proj[TOK * Cv];
__device__ float g_x1[TOK * Cv];
__device__ float g_hid[TOK * 4 * Cv];

// ---------------------------------------------------------------------------
// LayerNorm, warp-per-token, 8 tokens per 256-thread block, float4 I/O.
// mode 1: shifted/window-partitioned gather; mode 0: identity.
// ---------------------------------------------------------------------------
__global__ __launch_bounds__(256) void ln_kernel(
    const float* __restrict__ x, const float* __restrict__ gamma,
    const float* __restrict__ beta, float* __restrict__ out, int mode)
{
    int warp = threadIdx.x >> 5, lane = threadIdx.x & 31;
    int t = blockIdx.x * 8 + warp;

    int src;
    if (mode == 1) {
        int win = t / Nv, n = t % Nv;
        int b = win / NWIN, w = win % NWIN;
        int i = (w / 8) * WSv + n / WSv;
        int j = (w % 8) * WSv + n % WSv;
        int si = (i + SSv) % Hv;
        int sj = (j + SSv) % Wv;
        src = b * (Hv * Wv) + si * Wv + sj;
    } else {
        src = t;
    }

    const float4* xr = (const float4*)(x + (size_t)src * Cv);
    float4 v0 = xr[lane];
    float4 v1 = xr[lane + 32];

    float s  = v0.x + v0.y + v0.z + v0.w + v1.x + v1.y + v1.z + v1.w;
    float s2 = v0.x*v0.x + v0.y*v0.y + v0.z*v0.z + v0.w*v0.w
             + v1.x*v1.x + v1.y*v1.y + v1.z*v1.z + v1.w*v1.w;
    #pragma unroll
    for (int o = 16; o > 0; o >>= 1) {
        s  += __shfl_xor_sync(0xffffffffu, s,  o);
        s2 += __shfl_xor_sync(0xffffffffu, s2, o);
    }
    float mu   = s * (1.f / Cv);
    float var  = s2 * (1.f / Cv) - mu * mu;
    float rstd = rsqrtf(var + 1e-5f);

    const float4* gp = (const float4*)gamma;
    const float4* bp = (const float4*)beta;
    float4 g0 = gp[lane], g1 = gp[lane + 32];
    float4 b0 = bp[lane], b1 = bp[lane + 32];

    float4 o0, o1;
    o0.x = (v0.x - mu) * rstd * g0.x + b0.x;
    o0.y = (v0.y - mu) * rstd * g0.y + b0.y;
    o0.z = (v0.z - mu) * rstd * g0.z + b0.z;
    o0.w = (v0.w - mu) * rstd * g0.w + b0.w;
    o1.x = (v1.x - mu) * rstd * g1.x + b1.x;
    o1.y = (v1.y - mu) * rstd * g1.y + b1.y;
    o1.z = (v1.z - mu) * rstd * g1.z + b1.z;
    o1.w = (v1.w - mu) * rstd * g1.w + b1.w;

    float4* orow = (float4*)(out + (size_t)t * Cv);
    orow[lane]      = o0;
    orow[lane + 32] = o1;
}

// ---------------------------------------------------------------------------
// TF32 tensor-core GEMM (unchanged from R2).
// ---------------------------------------------------------------------------
#define PAD 4
__device__ __forceinline__ uint32_t f2tf32(float f) {
    uint32_t r;
    asm("cvt.rna.tf32.f32 %0, %1;" : "=r"(r) : "f"(f));
    return r;
}
__device__ __forceinline__ void mma_tf32(float* c, const uint32_t* a, const uint32_t* b) {
    asm volatile(
        "mma.sync.aligned.m16n8k8.row.col.f32.tf32.tf32.f32 "
        "{%0,%1,%2,%3}, {%4,%5,%6,%7}, {%8,%9}, {%0,%1,%2,%3};"
        : "+f"(c[0]), "+f"(c[1]), "+f"(c[2]), "+f"(c[3])
        : "r"(a[0]), "r"(a[1]), "r"(a[2]), "r"(a[3]), "r"(b[0]), "r"(b[1]));
}

__global__ __launch_bounds__(256) void tf32_gemm_kernel(
    const float* __restrict__ A, const float* __restrict__ Wt,
    const float* __restrict__ bias, const float* __restrict__ res,
    float* __restrict__ Cout, int M, int Nc, int K, int act)
{
    __shared__ uint32_t As[16][128 + PAD];
    __shared__ uint32_t Bs[16][128 + PAD];

    int tid  = threadIdx.x;
    int warp = tid >> 5, lane = tid & 31;
    int wm   = (warp >> 2) * 64;
    int wn   = (warp & 3) * 32;
    int bm   = blockIdx.y * 128, bn = blockIdx.x * 128;

    float acc[4][4][4];
    #pragma unroll
    for (int mt = 0; mt < 4; mt++)
        #pragma unroll
        for (int nt = 0; nt < 4; nt++)
            #pragma unroll
            for (int i = 0; i < 4; i++) acc[mt][nt][i] = 0.f;

    const float* Aptr = A  + (size_t)bm * K;
    const float* Bptr = Wt + (size_t)bn * K;

    int idx0 = tid, idx1 = tid + 256;
    int ar0 = idx0 >> 2, ac0 = (idx0 & 3) * 4;
    int ar1 = idx1 >> 2, ac1 = (idx1 & 3) * 4;

    float4 a_reg[2], b_reg[2];
    a_reg[0] = *(const float4*)(Aptr + (size_t)ar0 * K + ac0);
    a_reg[1] = *(const float4*)(Aptr + (size_t)ar1 * K + ac1);
    b_reg[0] = *(const float4*)(Bptr + (size_t)ar0 * K + ac0);
    b_reg[1] = *(const float4*)(Bptr + (size_t)ar1 * K + ac1);

    for (int k0 = 0; k0 < K; k0 += 16) {
        __syncthreads();
        As[ac0 + 0][ar0] = f2tf32(a_reg[0].x);
        As[ac0 + 1][ar0] = f2tf32(a_reg[0].y);
        As[ac0 + 2][ar0] = f2tf32(a_reg[0].z);
        As[ac0 + 3][ar0] = f2tf32(a_reg[0].w);
        As[ac1 + 0][ar1] = f2tf32(a_reg[1].x);
        As[ac1 + 1][ar1] = f2tf32(a_reg[1].y);
        As[ac1 + 2][ar1] = f2tf32(a_reg[1].z);
        As[ac1 + 3][ar1] = f2tf32(a_reg[1].w);
        Bs[ac0 + 0][ar0] = f2tf32(b_reg[0].x);
        Bs[ac0 + 1][ar0] = f2tf32(b_reg[0].y);
        Bs[ac0 + 2][ar0] = f2tf32(b_reg[0].z);
        Bs[ac0 + 3][ar0] = f2tf32(b_reg[0].w);
        Bs[ac1 + 0][ar1] = f2tf32(b_reg[1].x);
        Bs[ac1 + 1][ar1] = f2tf32(b_reg[1].y);
        Bs[ac1 + 2][ar1] = f2tf32(b_reg[1].z);
        Bs[ac1 + 3][ar1] = f2tf32(b_reg[1].w);
        __syncthreads();

        if (k0 + 16 < K) {
            int kn = k0 + 16;
            a_reg[0] = *(const float4*)(Aptr + (size_t)ar0 * K + kn + ac0);
            a_reg[1] = *(const float4*)(Aptr + (size_t)ar1 * K + kn + ac1);
            b_reg[0] = *(const float4*)(Bptr + (size_t)ar0 * K + kn + ac0);
            b_reg[1] = *(const float4*)(Bptr + (size_t)ar1 * K + kn + ac1);
        }

        #pragma unroll
        for (int ks = 0; ks < 2; ks++) {
            int kb = ks * 8;
            int qr = lane >> 2, qc = lane & 3;
            uint32_t af[4][4], bf[4][2];
            #pragma unroll
            for (int mt = 0; mt < 4; mt++) {
                int m = wm + mt * 16 + qr;
                af[mt][0] = As[kb + qc][m];
                af[mt][1] = As[kb + qc][m + 8];
                af[mt][2] = As[kb + qc + 4][m];
                af[mt][3] = As[kb + qc + 4][m + 8];
            }
            #pragma unroll
            for (int nt = 0; nt < 4; nt++) {
                int n = wn + nt * 8 + qr;
                bf[nt][0] = Bs[kb + qc][n];
                bf[nt][1] = Bs[kb + qc + 4][n];
            }
            #pragma unroll
            for (int mt = 0; mt < 4; mt++)
                #pragma unroll
                for (int nt = 0; nt < 4; nt++)
                    mma_tf32(acc[mt][nt], af[mt], bf[nt]);
        }
    }

    const float INV_SQRT2 = 0.70710678118654752f;
    int qr = lane >> 2, qc = lane & 3;
    #pragma unroll
    for (int mt = 0; mt < 4; mt++) {
        #pragma unroll
        for (int half = 0; half < 2; half++) {
            int row = bm + wm + mt * 16 + qr + half * 8;
            #pragma unroll
            for (int nt = 0; nt < 4; nt++) {
                int col = bn + wn + nt * 8 + qc * 2;
                float v0 = acc[mt][nt][half * 2 + 0];
                float v1 = acc[mt][nt][half * 2 + 1];
                if (bias) { v0 += bias[col]; v1 += bias[col + 1]; }
                if (act == 1) {
                    v0 = 0.5f * v0 * (1.f + erff(v0 * INV_SQRT2));
                    v1 = 0.5f * v1 * (1.f + erff(v1 * INV_SQRT2));
                }
                size_t oidx = (size_t)row * Nc + col;
                if (res) { v0 += res[oidx]; v1 += res[oidx + 1]; }
                *(float2*)(Cout + oidx) = make_float2(v0, v1);
            }
        }
    }
}

// ---------------------------------------------------------------------------
// Window attention: one block per (window, head). 256 threads.
// K stored transposed in smem (kst[d][m], stride 49) -> conflict-free QK.
// ---------------------------------------------------------------------------
__global__ __launch_bounds__(256) void attn_kernel(
    const float* __restrict__ qkv, const float* __restrict__ rel_bias,
    const float* __restrict__ mask, float* __restrict__ out)
{
    int blk  = blockIdx.x;
    int win  = blk >> 3;
    int head = blk & 7;
    int tid  = threadIdx.x;

    __shared__ float qs[Nv * HDv];    // [n][d], stride 32 (QK reads broadcast)
    __shared__ float kst[HDv * Nv];   // [d][m], stride 49 (conflict-free)
    __shared__ float vs[Nv * HDv];    // [m][d]
    __shared__ float att[Nv * Nv];    // [n][m], stride 49

    int base = win * Nv;
    for (int idx = tid; idx < Nv * HDv; idx += 256) {
        int n = idx >> 5, d = idx & 31;
        int row = (base + n) * (3 * Cv);
        int f   = head * HDv + d;
        qs[idx]          = qkv[row + f] * SCALEv;
        kst[d * Nv + n]  = qkv[row + Cv + f];
        vs[idx]          = qkv[row + 2 * Cv + f];
    }
    __syncthreads();

    int wm = win % NWIN;
    for (int e = tid; e < Nv * Nv; e += 256) {
        int n = e / Nv, m = e % Nv;
        float s = 0.f;
        #pragma unroll
        for (int d = 0; d < HDv; d++)
            s = fmaf(qs[n * HDv + d], kst[d * Nv + m], s);
        int r1 = n / WSv, c1 = n % WSv;
        int r2 = m / WSv, c2 = m % WSv;
        int bi = (r1 - r2 + WSv - 1) * (2 * WSv - 1) + (c1 - c2 + WSv - 1);
        s += rel_bias[bi * NHv + head] + mask[wm * (Nv * Nv) + e];
        att[e] = s;
    }
    __syncthreads();

    if (tid < Nv) {
        float mx = -1e30f;
        #pragma unroll 7
        for (int m = 0; m < Nv; m++) mx = fmaxf(mx, att[tid * Nv + m]);
        float sum = 0.f;
        #pragma unroll 7
        for (int m = 0; m < Nv; m++) {
            float e2 = __expf(att[tid * Nv + m] - mx);
            att[tid * Nv + m] = e2;
            sum += e2;
        }
        float inv = 1.f / sum;
        #pragma unroll 7
        for (int m = 0; m < Nv; m++) att[tid * Nv + m] *= inv;
    }
    __syncthreads();

    for (int idx = tid; idx < Nv * HDv; idx += 256) {
        int n = idx >> 5, d = idx & 31;
        float s = 0.f;
        #pragma unroll 7
        for (int m = 0; m < Nv; m++)
            s = fmaf(att[n * Nv + m], vs[m * HDv + d], s);
        out[(size_t)(base + n) * Cv + head * HDv + d] = s;
    }
}

// ---------------------------------------------------------------------------
// Window-reverse + unshift + residual, 4 tokens per 256-thread block, float4.
// ---------------------------------------------------------------------------
__global__ __launch_bounds__(256) void unshift_add_kernel(
    const float* __restrict__ x, const float* __restrict__ proj,
    float* __restrict__ x1)
{
    int tok = blockIdx.x * 4 + (threadIdx.x >> 6);
    int c4  = threadIdx.x & 63;
    int b = tok / (Hv * Wv);
    int ij = tok % (Hv * Wv);
    int i = ij / Wv, j = ij % Wv;
    int p = (i + Hv - SSv) % Hv;
    int q = (j + Wv - SSv) % Wv;
    int win = b * NWIN + (p / WSv) * 8 + (q / WSv);
    int n   = (p % WSv) * WSv + (q % WSv);

    const float4* xr = (const float4*)(x    + (size_t)tok * Cv);
    const float4* pr = (const float4*)(proj + (size_t)(win * Nv + n) * Cv);
    float4* orow     = (float4*)(x1 + (size_t)tok * Cv);
    float4 a = xr[c4], bb = pr[c4];
    a.x += bb.x; a.y += bb.y; a.z += bb.z; a.w += bb.w;
    orow[c4] = a;
}

// ---------------------------------------------------------------------------
extern "C" void kernel_launch(void* const* d_in, const int* in_sizes, int n_in,
                              void* d_out, int out_size)
{
    const float* x       = (const float*)d_in[0];
    const float* mask    = (const float*)d_in[1];
    const float* norm1_g = (const float*)d_in[2];
    const float* norm1_b = (const float*)d_in[3];
    const float* qkv_w   = (const float*)d_in[4];
    const float* qkv_b   = (const float*)d_in[5];
    const float* rel_bias= (const float*)d_in[6];
    const float* proj_w  = (const float*)d_in[7];
    const float* proj_b  = (const float*)d_in[8];
    const float* norm2_g = (const float*)d_in[9];
    const float* norm2_b = (const float*)d_in[10];
    const float* fc1_w   = (const float*)d_in[11];
    const float* fc1_b   = (const float*)d_in[12];
    const float* fc2_w   = (const float*)d_in[13];
    const float* fc2_b   = (const float*)d_in[14];
    float* out = (float*)d_out;

    float *p_win, *p_qkv, *p_atto, *p_proj, *p_x1, *p_hid;
    cudaGetSymbolAddress((void**)&p_win,  g_win);
    cudaGetSymbolAddress((void**)&p_qkv,  g_qkv);
    cudaGetSymbolAddress((void**)&p_atto, g_atto);
    cudaGetSymbolAddress((void**)&p_proj, g_proj);
    cudaGetSymbolAddress((void**)&p_x1,   g_x1);
    cudaGetSymbolAddress((void**)&p_hid,  g_hid);

    // 1. LN1 + shift + window partition (8 tokens / block)
    ln_kernel<<<TOK / 8, 256>>>(x, norm1_g, norm1_b, p_win, 1);

    // 2. QKV GEMM
    {
        dim3 grid(3 * Cv / 128, TOK / 128);
        tf32_gemm_kernel<<<grid, 256>>>(p_win, qkv_w, qkv_b, nullptr, p_qkv,
                                        TOK, 3 * Cv, Cv, 0);
    }

    // 3. window attention
    attn_kernel<<<BW * NHv, 256>>>(p_qkv, rel_bias, mask, p_atto);

    // 4. proj GEMM
    {
        dim3 grid(Cv / 128, TOK / 128);
        tf32_gemm_kernel<<<grid, 256>>>(p_atto, proj_w, proj_b, nullptr, p_proj,
                                        TOK, Cv, Cv, 0);
    }

    // 5. window reverse + unshift + residual -> x1
    unshift_add_kernel<<<TOK / 4, 256>>>(x, p_proj, p_x1);

    // 6. LN2
    ln_kernel<<<TOK / 8, 256>>>(p_x1, norm2_g, norm2_b, p_win, 0);

    // 7. fc1 GEMM + GELU
    {
        dim3 grid(4 * Cv / 128, TOK / 128);
        tf32_gemm_kernel<<<grid, 256>>>(p_win, fc1_w, fc1_b, nullptr, p_hid,
                                        TOK, 4 * Cv, Cv, 1);
    }

    // 8. fc2 GEMM + residual(x1) -> out
    {
        dim3 grid(Cv / 128, TOK / 128);
        tf32_gemm_kernel<<<grid, 256>>>(p_hid, fc2_w, fc2_b, p_x1, out,
                                        TOK, Cv, 4 * Cv, 0);
    }
}